// round 11
// baseline (speedup 1.0000x reference)
#include <cuda_runtime.h>
#include <cstdint>

#define BATCH 8
#define NN 2048
#define FF 128

// ---------------- scratch (static device globals; no allocation) ----------------
__device__ float g_h[BATCH * NN * FF];                 // h, then h2 = tf32(h*invD) in place
__device__ float g_s1[BATCH * NN], g_s2p[BATCH * NN];  // s1, s2 + b_a
__device__ float g_u1[BATCH * NN], g_u2[BATCH * NN];   // exp(s1), exp(s2p)
__device__ float g_v1[BATCH * NN], g_v2[BATCH * NN];   // exp(0.2 s1), exp(0.2 s2p)
__device__ float g_DU[BATCH * NN], g_DV[BATCH * NN];   // column partial sums
__device__ float4 g_js[BATCH * NN];                    // packed j-stats (s2p, u2, v2, 0)
__device__ unsigned g_maskT[BATCH * (NN / 32) * NN];   // adjacency bitmask TRANSPOSED [b][word][i]

__device__ __forceinline__ unsigned f2tf32(float f) {
    unsigned u;
    asm("cvt.rna.tf32.f32 %0, %1;" : "=r"(u) : "f"(f));
    return u;
}

__device__ __forceinline__ void mma_tf32(float* d, const unsigned* a, const unsigned* b) {
    asm volatile(
        "mma.sync.aligned.m16n8k8.row.col.f32.tf32.tf32.f32 "
        "{%0,%1,%2,%3}, {%4,%5,%6,%7}, {%8,%9}, {%0,%1,%2,%3};\n"
        : "+f"(d[0]), "+f"(d[1]), "+f"(d[2]), "+f"(d[3])
        : "r"(a[0]), "r"(a[1]), "r"(a[2]), "r"(a[3]), "r"(b[0]), "r"(b[1]));
}

#define CP_ASYNC16(dst, src) \
    asm volatile("cp.async.cg.shared.global [%0], [%1], 16;\n" ::"r"(dst), "l"(src))
#define CP_COMMIT() asm volatile("cp.async.commit_group;\n")
#define CP_WAIT(n) asm volatile("cp.async.wait_group %0;\n" ::"n"(n))

// ---------------- kernel 1: h = x @ W + b_W, fused row stats + DU/DV zeroing ----------------
__global__ __launch_bounds__(256) void k_gemm_h(const float* __restrict__ x,
                                                const float* __restrict__ W,
                                                const float* __restrict__ bW,
                                                const float* __restrict__ a1,
                                                const float* __restrict__ a2,
                                                const float* __restrict__ ba) {
    __shared__ float XsT[32][68];   // [k][m] transposed, padded
    __shared__ float Ws[32][128];   // [k][n]
    const int t = threadIdx.x;
    const int tx = t & 15, ty = t >> 4;
    const int m0 = blockIdx.x * 64;

    if (t < 64) {  // zero this block's slice of the column-sum accumulators
        g_DU[m0 + t] = 0.f;
        g_DV[m0 + t] = 0.f;
    }

    float acc[4][8];
#pragma unroll
    for (int i = 0; i < 4; i++)
#pragma unroll
        for (int j = 0; j < 8; j++) acc[i][j] = 0.f;

    for (int k0 = 0; k0 < 128; k0 += 32) {
#pragma unroll
        for (int it = 0; it < 2; it++) {
            int q = t + it * 256;
            int rr = q >> 3, c4 = q & 7;
            float4 v = *(const float4*)&x[(m0 + rr) * 128 + k0 + c4 * 4];
            XsT[c4 * 4 + 0][rr] = v.x;
            XsT[c4 * 4 + 1][rr] = v.y;
            XsT[c4 * 4 + 2][rr] = v.z;
            XsT[c4 * 4 + 3][rr] = v.w;
        }
#pragma unroll
        for (int it = 0; it < 4; it++) {
            int q = t + it * 256;
            int rr = q >> 5, c4 = q & 31;
            *(float4*)&Ws[rr][c4 * 4] = *(const float4*)&W[(k0 + rr) * 128 + c4 * 4];
        }
        __syncthreads();
#pragma unroll
        for (int kk = 0; kk < 32; kk++) {
            float4 a = *(float4*)&XsT[kk][ty * 4];
            float4 b0 = *(float4*)&Ws[kk][tx * 4];
            float4 b1 = *(float4*)&Ws[kk][64 + tx * 4];
            float aa[4] = {a.x, a.y, a.z, a.w};
            float bb[8] = {b0.x, b0.y, b0.z, b0.w, b1.x, b1.y, b1.z, b1.w};
#pragma unroll
            for (int i = 0; i < 4; i++)
#pragma unroll
                for (int j = 0; j < 8; j++) acc[i][j] = fmaf(aa[i], bb[j], acc[i][j]);
        }
        __syncthreads();
    }

    float4 bwA = *(const float4*)&bW[tx * 4];
    float4 bwB = *(const float4*)&bW[64 + tx * 4];
    float4 a1A = *(const float4*)&a1[tx * 4];
    float4 a1B = *(const float4*)&a1[64 + tx * 4];
    float4 a2A = *(const float4*)&a2[tx * 4];
    float4 a2B = *(const float4*)&a2[64 + tx * 4];

    float p1[4], p2[4];
#pragma unroll
    for (int i = 0; i < 4; i++) {
        int row = m0 + ty * 4 + i;
        float4 o0 = {acc[i][0] + bwA.x, acc[i][1] + bwA.y, acc[i][2] + bwA.z, acc[i][3] + bwA.w};
        float4 o1 = {acc[i][4] + bwB.x, acc[i][5] + bwB.y, acc[i][6] + bwB.z, acc[i][7] + bwB.w};
        *(float4*)&g_h[row * 128 + tx * 4] = o0;
        *(float4*)&g_h[row * 128 + 64 + tx * 4] = o1;
        p1[i] = o0.x * a1A.x + o0.y * a1A.y + o0.z * a1A.z + o0.w * a1A.w +
                o1.x * a1B.x + o1.y * a1B.y + o1.z * a1B.z + o1.w * a1B.w;
        p2[i] = o0.x * a2A.x + o0.y * a2A.y + o0.z * a2A.z + o0.w * a2A.w +
                o1.x * a2B.x + o1.y * a2B.y + o1.z * a2B.z + o1.w * a2B.w;
    }
#pragma unroll
    for (int off = 8; off > 0; off >>= 1) {
#pragma unroll
        for (int i = 0; i < 4; i++) {
            p1[i] += __shfl_down_sync(0xffffffffu, p1[i], off);
            p2[i] += __shfl_down_sync(0xffffffffu, p2[i], off);
        }
    }
    if (tx == 0) {
        float ba0 = ba[0];
#pragma unroll
        for (int i = 0; i < 4; i++) {
            int row = m0 + ty * 4 + i;
            float s1v = p1[i];
            float s2pv = p2[i] + ba0;
            g_s1[row] = s1v;
            g_s2p[row] = s2pv;
            g_u1[row] = expf(s1v);
            g_u2[row] = expf(s2pv);
            g_v1[row] = expf(0.2f * s1v);
            g_v2[row] = expf(0.2f * s2pv);
        }
    }
}

// ---------------- kernel 2: fused adj pack (transposed bitmask) + column sums ----------------
// grid (4, 32, 8): x = 512-col block, y = 64-row chunk, z = batch. 128 thr, 4 cols/thread.
__global__ __launch_bounds__(128) void k_pack(const int* __restrict__ adj) {
    const int t = threadIdx.x;
    const int jb = blockIdx.x, ic = blockIdx.y, b = blockIdx.z;
    const int i0 = ic * 64;
    const int nb = b * NN;
    __shared__ float s1s[64], u1s[64], v1s[64];
    if (t < 64) {
        s1s[t] = g_s1[nb + i0 + t];
        u1s[t] = g_u1[nb + i0 + t];
        v1s[t] = g_v1[nb + i0 + t];
    }
    __syncthreads();

    const int jloc = jb * 512 + t * 4;
    const int sub = t & 7;
    float s2p[4], accU[4], accV[4];
#pragma unroll
    for (int q = 0; q < 4; q++) {
        s2p[q] = g_s2p[nb + jloc + q];
        accU[q] = 0.f;
        accV[q] = 0.f;
    }
    const int4* arow = (const int4*)(adj + (size_t)b * NN * NN + (size_t)i0 * NN + jb * 512);
    // transposed mask: [b][word][i]; this block writes word jb*16 + (t>>3) for rows i0..i0+63
    unsigned* mcol = g_maskT + ((size_t)b * 64 + jb * 16 + (t >> 3)) * NN + i0;
    const int stride4 = NN / 4;

#pragma unroll 4
    for (int ii = 0; ii < 64; ii++) {
        int4 av = arow[ii * stride4 + t];
        bool m0 = av.x > 0, m1 = av.y > 0, m2 = av.z > 0, m3 = av.w > 0;
        unsigned nib = (m0 ? 1u : 0u) | (m1 ? 2u : 0u) | (m2 ? 4u : 0u) | (m3 ? 8u : 0u);
        unsigned w = nib << (sub * 4);
        w |= __shfl_xor_sync(0xffffffffu, w, 1);
        w |= __shfl_xor_sync(0xffffffffu, w, 2);
        w |= __shfl_xor_sync(0xffffffffu, w, 4);
        if (sub == 0) mcol[ii] = w;

        float s1i = s1s[ii], u1i = u1s[ii], v1i = v1s[ii];
        bool mm[4] = {m0, m1, m2, m3};
#pragma unroll
        for (int q = 0; q < 4; q++) {
            float tt = s1i + s2p[q];
            accU[q] += (mm[q] && tt > 0.f) ? u1i : 0.f;
            accV[q] += (mm[q] && tt <= 0.f) ? v1i : 0.f;
        }
    }
#pragma unroll
    for (int q = 0; q < 4; q++) {
        atomicAdd(&g_DU[nb + jloc + q], accU[q]);
        atomicAdd(&g_DV[nb + jloc + q], accV[q]);
    }
}

// ---------------- kernel 3: h2 = tf32(h * invD[row]) in place; pack g_js ----------------
__global__ __launch_bounds__(256) void k_scale() {
    int idx = blockIdx.x * 256 + threadIdx.x;  // float4 index, 524288 total
    int row = idx >> 5;
    float d = g_u2[row] * g_DU[row] + g_v2[row] * g_DV[row];
    float inv = (d != 0.f) ? (1.f / d) : 0.f;  // guard fully-masked columns
    float4* hp = (float4*)g_h;
    float4 v = hp[idx];
    v.x = __uint_as_float(f2tf32(v.x * inv));
    v.y = __uint_as_float(f2tf32(v.y * inv));
    v.z = __uint_as_float(f2tf32(v.z * inv));
    v.w = __uint_as_float(f2tf32(v.w * inv));
    hp[idx] = v;
    if ((idx & 31) == 0) {
        g_js[row] = make_float4(g_s2p[row], g_u2[row], g_v2[row], 0.f);
    }
}

// ---------------- kernel 4: out = relu(P @ h2), P tile built cooperatively in smem ----------------
// grid (32, 8): x = 64-row i-block, y = batch. 512 thr = 16 warps: 4(M=16) x 4(N=32).
// Pipeline per kt: cp.async {h2 tile, j-stats, mask col} ; all threads build 64x32 P tile in smem
// (once, no cross-warp redundancy) ; warps run m16n8k8 tf32 mma from smem.
#define P_STRIDE 36  // bank = (4*row + j) % 32 -> conflict-free A-frag LDS

__global__ __launch_bounds__(512, 2) void k_attn(float* __restrict__ out) {
    extern __shared__ float smraw[];
    float* hs = smraw;                                   // 2 x [32][136] = 34816 B
    float* pbuf = smraw + 2 * 32 * 136;                  // 2 x [64][36]  = 18432 B
    float4* jstage = (float4*)(pbuf + 2 * 64 * P_STRIDE);  // 2 x [32] float4 = 1024 B
    unsigned* mstage = (unsigned*)(jstage + 64);         // 2 x [64] words  = 512 B

    const int b = blockIdx.y;
    const int i0 = blockIdx.x * 64;
    const int t = threadIdx.x;
    const int lane = t & 31, wid = t >> 5;
    const int wm = wid & 3, wn = wid >> 2;
    const int r = lane >> 2, c = lane & 3;
    const int nb = b * NN;

    // P-compute assignment: thread -> (local row ip, 4 j's starting at jp4)
    const int ip = t >> 3, jp4 = (t & 7) * 4;
    const float s1i = g_s1[nb + i0 + ip];
    const float u1i = g_u1[nb + i0 + ip];
    const float v1i = g_v1[nb + i0 + ip];

    const float* hsrc = g_h + (size_t)nb * FF;
    const float4* jsrc_it = g_js + nb;                              // advances 32/tile
    const unsigned* msrc_it = g_maskT + (size_t)b * 64 * NN + i0;   // advances NN/tile

    // cp.async mapping: 1024 16B chunks of Hs; each thread does 2.
    const int q0 = t, q1 = t + 512;
    const int r0 = q0 >> 5, c0 = (q0 & 31) * 4;
    const int r1 = q1 >> 5, c1 = (q1 & 31) * 4;
    const float* hsrc0 = hsrc + (size_t)r0 * FF + c0;  // advances 32*FF/tile
    const float* hsrc1 = hsrc + (size_t)r1 * FF + c1;

    float acc[4][4];
#pragma unroll
    for (int nt = 0; nt < 4; nt++)
#pragma unroll
        for (int q = 0; q < 4; q++) acc[nt][q] = 0.f;

    // prefetch tile 0
    {
        unsigned d0 = (unsigned)__cvta_generic_to_shared(hs + r0 * 136 + c0);
        unsigned d1 = (unsigned)__cvta_generic_to_shared(hs + r1 * 136 + c1);
        CP_ASYNC16(d0, hsrc0);
        CP_ASYNC16(d1, hsrc1);
        if (t < 32) {
            unsigned dj = (unsigned)__cvta_generic_to_shared(jstage + t);
            CP_ASYNC16(dj, jsrc_it + t);
        } else if (t < 48) {
            unsigned dm = (unsigned)__cvta_generic_to_shared(mstage + (t - 32) * 4);
            CP_ASYNC16(dm, msrc_it + (t - 32) * 4);
        }
        CP_COMMIT();
    }

    for (int kt = 0; kt < 64; kt++) {
        const int par = kt & 1;
        CP_WAIT(0);
        __syncthreads();

        // prefetch next tile (writes the other buffer; all readers of it passed the barrier)
        if (kt < 63) {
            const int nxt = (kt + 1) & 1;
            hsrc0 += 32 * FF;
            hsrc1 += 32 * FF;
            jsrc_it += 32;
            msrc_it += NN;
            unsigned d0 = (unsigned)__cvta_generic_to_shared(hs + nxt * 4352 + r0 * 136 + c0);
            unsigned d1 = (unsigned)__cvta_generic_to_shared(hs + nxt * 4352 + r1 * 136 + c1);
            CP_ASYNC16(d0, hsrc0);
            CP_ASYNC16(d1, hsrc1);
            if (t < 32) {
                unsigned dj = (unsigned)__cvta_generic_to_shared(jstage + nxt * 32 + t);
                CP_ASYNC16(dj, jsrc_it + t);
            } else if (t < 48) {
                unsigned dm = (unsigned)__cvta_generic_to_shared(mstage + nxt * 64 + (t - 32) * 4);
                CP_ASYNC16(dm, msrc_it + (t - 32) * 4);
            }
            CP_COMMIT();
        }

        // ---- cooperative P tile: 64 x 32, each thread 4 values ----
        {
            const unsigned mw = mstage[par * 64 + ip];
            const float4* J = jstage + par * 32 + jp4;
            float pv[4];
#pragma unroll
            for (int q = 0; q < 4; q++) {
                float4 ja = J[q];
                float tt = s1i + ja.x;
                float p = (tt > 0.f) ? u1i * ja.y : v1i * ja.z;
                p = ((mw >> (jp4 + q)) & 1u) ? p : 0.f;
                pv[q] = __uint_as_float(f2tf32(p));
            }
            *(float4*)&pbuf[par * 64 * P_STRIDE + ip * P_STRIDE + jp4] =
                make_float4(pv[0], pv[1], pv[2], pv[3]);
        }
        __syncthreads();

        const float* H = hs + par * 4352;
        const float* P = pbuf + par * 64 * P_STRIDE;

#pragma unroll
        for (int ks = 0; ks < 4; ks++) {
            const int bp = ks * 8 + c;
            unsigned afr[4];
            afr[0] = __float_as_uint(P[(wm * 16 + r) * P_STRIDE + bp]);
            afr[1] = __float_as_uint(P[(wm * 16 + r + 8) * P_STRIDE + bp]);
            afr[2] = __float_as_uint(P[(wm * 16 + r) * P_STRIDE + bp + 4]);
            afr[3] = __float_as_uint(P[(wm * 16 + r + 8) * P_STRIDE + bp + 4]);

#pragma unroll
            for (int nt = 0; nt < 4; nt++) {
                const int col = wn * 32 + nt * 8 + r;
                unsigned bb[2];
                bb[0] = __float_as_uint(H[bp * 136 + col]);
                bb[1] = __float_as_uint(H[(bp + 4) * 136 + col]);
                mma_tf32(acc[nt], afr, bb);
            }
        }
    }

    const int rA = i0 + wm * 16 + r, rB = rA + 8;
#pragma unroll
    for (int nt = 0; nt < 4; nt++) {
        int col = wn * 32 + nt * 8 + 2 * c;
        float2 o0 = {fmaxf(acc[nt][0], 0.f), fmaxf(acc[nt][1], 0.f)};
        float2 o1 = {fmaxf(acc[nt][2], 0.f), fmaxf(acc[nt][3], 0.f)};
        *(float2*)&out[(size_t)(nb + rA) * FF + col] = o0;
        *(float2*)&out[(size_t)(nb + rB) * FF + col] = o1;
    }
}

// ---------------- launch ----------------
extern "C" void kernel_launch(void* const* d_in, const int* in_sizes, int n_in,
                              void* d_out, int out_size) {
    const float* x = (const float*)d_in[0];
    const int* adj = (const int*)d_in[1];
    const float* W = (const float*)d_in[2];
    const float* bW = (const float*)d_in[3];
    const float* a1 = (const float*)d_in[4];
    const float* a2 = (const float*)d_in[5];
    const float* ba = (const float*)d_in[6];
    float* out = (float*)d_out;

    const int smem_attn = (2 * 32 * 136 + 2 * 64 * P_STRIDE) * 4 + 2 * 32 * 16 + 2 * 64 * 4;
    static bool attr_set = false;
    if (!attr_set) {
        cudaFuncSetAttribute(k_attn, cudaFuncAttributeMaxDynamicSharedMemorySize, smem_attn);
        attr_set = true;
    }

    k_gemm_h<<<256, 256>>>(x, W, bW, a1, a2, ba);
    k_pack<<<dim3(4, 32, 8), 128>>>(adj);
    k_scale<<<2048, 256>>>();
    k_attn<<<dim3(32, 8), 512, smem_attn>>>(out);
}

// round 12
// speedup vs baseline: 1.2653x; 1.2653x over previous
#include <cuda_runtime.h>
#include <cstdint>

#define BATCH 8
#define NN 2048
#define FF 128

// ---------------- scratch (static device globals; no allocation) ----------------
__device__ float g_h[BATCH * NN * FF];                 // h, then h2 = tf32(h*invD) in place
__device__ float g_s1[BATCH * NN], g_s2p[BATCH * NN];  // s1, s2 + b_a
__device__ float g_u1[BATCH * NN], g_u2[BATCH * NN];   // exp(s1), exp(s2p)
__device__ float g_v1[BATCH * NN], g_v2[BATCH * NN];   // exp(0.2 s1), exp(0.2 s2p)
__device__ float g_DU[BATCH * NN], g_DV[BATCH * NN];   // column partial sums
__device__ float4 g_js[BATCH * NN];                    // packed j-stats (s2p, u2, v2, 0)
__device__ unsigned g_maskT[BATCH * (NN / 32) * NN];   // adjacency bitmask TRANSPOSED [b][word][i]

__device__ __forceinline__ unsigned f2tf32(float f) {
    unsigned u;
    asm("cvt.rna.tf32.f32 %0, %1;" : "=r"(u) : "f"(f));
    return u;
}

__device__ __forceinline__ void mma_tf32(float* d, const unsigned* a, const unsigned* b) {
    asm volatile(
        "mma.sync.aligned.m16n8k8.row.col.f32.tf32.tf32.f32 "
        "{%0,%1,%2,%3}, {%4,%5,%6,%7}, {%8,%9}, {%0,%1,%2,%3};\n"
        : "+f"(d[0]), "+f"(d[1]), "+f"(d[2]), "+f"(d[3])
        : "r"(a[0]), "r"(a[1]), "r"(a[2]), "r"(a[3]), "r"(b[0]), "r"(b[1]));
}

#define CP_ASYNC16(dst, src) \
    asm volatile("cp.async.cg.shared.global [%0], [%1], 16;\n" ::"r"(dst), "l"(src))
#define CP_COMMIT() asm volatile("cp.async.commit_group;\n")
#define CP_WAIT(n) asm volatile("cp.async.wait_group %0;\n" ::"n"(n))

// ---------------- kernel 1: h = x @ W + b_W, fused row stats + DU/DV zeroing ----------------
__global__ __launch_bounds__(256) void k_gemm_h(const float* __restrict__ x,
                                                const float* __restrict__ W,
                                                const float* __restrict__ bW,
                                                const float* __restrict__ a1,
                                                const float* __restrict__ a2,
                                                const float* __restrict__ ba) {
    __shared__ float XsT[32][68];   // [k][m] transposed, padded
    __shared__ float Ws[32][128];   // [k][n]
    const int t = threadIdx.x;
    const int tx = t & 15, ty = t >> 4;
    const int m0 = blockIdx.x * 64;

    if (t < 64) {  // zero this block's slice of the column-sum accumulators
        g_DU[m0 + t] = 0.f;
        g_DV[m0 + t] = 0.f;
    }

    float acc[4][8];
#pragma unroll
    for (int i = 0; i < 4; i++)
#pragma unroll
        for (int j = 0; j < 8; j++) acc[i][j] = 0.f;

    for (int k0 = 0; k0 < 128; k0 += 32) {
#pragma unroll
        for (int it = 0; it < 2; it++) {
            int q = t + it * 256;
            int rr = q >> 3, c4 = q & 7;
            float4 v = *(const float4*)&x[(m0 + rr) * 128 + k0 + c4 * 4];
            XsT[c4 * 4 + 0][rr] = v.x;
            XsT[c4 * 4 + 1][rr] = v.y;
            XsT[c4 * 4 + 2][rr] = v.z;
            XsT[c4 * 4 + 3][rr] = v.w;
        }
#pragma unroll
        for (int it = 0; it < 4; it++) {
            int q = t + it * 256;
            int rr = q >> 5, c4 = q & 31;
            *(float4*)&Ws[rr][c4 * 4] = *(const float4*)&W[(k0 + rr) * 128 + c4 * 4];
        }
        __syncthreads();
#pragma unroll
        for (int kk = 0; kk < 32; kk++) {
            float4 a = *(float4*)&XsT[kk][ty * 4];
            float4 b0 = *(float4*)&Ws[kk][tx * 4];
            float4 b1 = *(float4*)&Ws[kk][64 + tx * 4];
            float aa[4] = {a.x, a.y, a.z, a.w};
            float bb[8] = {b0.x, b0.y, b0.z, b0.w, b1.x, b1.y, b1.z, b1.w};
#pragma unroll
            for (int i = 0; i < 4; i++)
#pragma unroll
                for (int j = 0; j < 8; j++) acc[i][j] = fmaf(aa[i], bb[j], acc[i][j]);
        }
        __syncthreads();
    }

    float4 bwA = *(const float4*)&bW[tx * 4];
    float4 bwB = *(const float4*)&bW[64 + tx * 4];
    float4 a1A = *(const float4*)&a1[tx * 4];
    float4 a1B = *(const float4*)&a1[64 + tx * 4];
    float4 a2A = *(const float4*)&a2[tx * 4];
    float4 a2B = *(const float4*)&a2[64 + tx * 4];

    float p1[4], p2[4];
#pragma unroll
    for (int i = 0; i < 4; i++) {
        int row = m0 + ty * 4 + i;
        float4 o0 = {acc[i][0] + bwA.x, acc[i][1] + bwA.y, acc[i][2] + bwA.z, acc[i][3] + bwA.w};
        float4 o1 = {acc[i][4] + bwB.x, acc[i][5] + bwB.y, acc[i][6] + bwB.z, acc[i][7] + bwB.w};
        *(float4*)&g_h[row * 128 + tx * 4] = o0;
        *(float4*)&g_h[row * 128 + 64 + tx * 4] = o1;
        p1[i] = o0.x * a1A.x + o0.y * a1A.y + o0.z * a1A.z + o0.w * a1A.w +
                o1.x * a1B.x + o1.y * a1B.y + o1.z * a1B.z + o1.w * a1B.w;
        p2[i] = o0.x * a2A.x + o0.y * a2A.y + o0.z * a2A.z + o0.w * a2A.w +
                o1.x * a2B.x + o1.y * a2B.y + o1.z * a2B.z + o1.w * a2B.w;
    }
#pragma unroll
    for (int off = 8; off > 0; off >>= 1) {
#pragma unroll
        for (int i = 0; i < 4; i++) {
            p1[i] += __shfl_down_sync(0xffffffffu, p1[i], off);
            p2[i] += __shfl_down_sync(0xffffffffu, p2[i], off);
        }
    }
    if (tx == 0) {
        float ba0 = ba[0];
#pragma unroll
        for (int i = 0; i < 4; i++) {
            int row = m0 + ty * 4 + i;
            float s1v = p1[i];
            float s2pv = p2[i] + ba0;
            g_s1[row] = s1v;
            g_s2p[row] = s2pv;
            g_u1[row] = expf(s1v);
            g_u2[row] = expf(s2pv);
            g_v1[row] = expf(0.2f * s1v);
            g_v2[row] = expf(0.2f * s2pv);
        }
    }
}

// ---------------- kernel 2: fused adj pack (transposed bitmask) + column sums ----------------
// grid (4, 32, 8): x = 512-col block, y = 64-row chunk, z = batch. 128 thr, 4 cols/thread.
__global__ __launch_bounds__(128) void k_pack(const int* __restrict__ adj) {
    const int t = threadIdx.x;
    const int jb = blockIdx.x, ic = blockIdx.y, b = blockIdx.z;
    const int i0 = ic * 64;
    const int nb = b * NN;
    __shared__ float s1s[64], u1s[64], v1s[64];
    if (t < 64) {
        s1s[t] = g_s1[nb + i0 + t];
        u1s[t] = g_u1[nb + i0 + t];
        v1s[t] = g_v1[nb + i0 + t];
    }
    __syncthreads();

    const int jloc = jb * 512 + t * 4;
    const int sub = t & 7;
    float s2p[4], accU[4], accV[4];
#pragma unroll
    for (int q = 0; q < 4; q++) {
        s2p[q] = g_s2p[nb + jloc + q];
        accU[q] = 0.f;
        accV[q] = 0.f;
    }
    const int4* arow = (const int4*)(adj + (size_t)b * NN * NN + (size_t)i0 * NN + jb * 512);
    // transposed mask: [b][word][i]; this block writes word jb*16 + (t>>3) for rows i0..i0+63
    unsigned* mcol = g_maskT + ((size_t)b * 64 + jb * 16 + (t >> 3)) * NN + i0;
    const int stride4 = NN / 4;

#pragma unroll 4
    for (int ii = 0; ii < 64; ii++) {
        int4 av = arow[ii * stride4 + t];
        bool m0 = av.x > 0, m1 = av.y > 0, m2 = av.z > 0, m3 = av.w > 0;
        unsigned nib = (m0 ? 1u : 0u) | (m1 ? 2u : 0u) | (m2 ? 4u : 0u) | (m3 ? 8u : 0u);
        unsigned w = nib << (sub * 4);
        w |= __shfl_xor_sync(0xffffffffu, w, 1);
        w |= __shfl_xor_sync(0xffffffffu, w, 2);
        w |= __shfl_xor_sync(0xffffffffu, w, 4);
        if (sub == 0) mcol[ii] = w;

        float s1i = s1s[ii], u1i = u1s[ii], v1i = v1s[ii];
        bool mm[4] = {m0, m1, m2, m3};
#pragma unroll
        for (int q = 0; q < 4; q++) {
            float tt = s1i + s2p[q];
            accU[q] += (mm[q] && tt > 0.f) ? u1i : 0.f;
            accV[q] += (mm[q] && tt <= 0.f) ? v1i : 0.f;
        }
    }
#pragma unroll
    for (int q = 0; q < 4; q++) {
        atomicAdd(&g_DU[nb + jloc + q], accU[q]);
        atomicAdd(&g_DV[nb + jloc + q], accV[q]);
    }
}

// ---------------- kernel 3: h2 = tf32(h * invD[row]) in place; pack g_js ----------------
__global__ __launch_bounds__(256) void k_scale() {
    int idx = blockIdx.x * 256 + threadIdx.x;  // float4 index, 524288 total
    int row = idx >> 5;
    float d = g_u2[row] * g_DU[row] + g_v2[row] * g_DV[row];
    float inv = (d != 0.f) ? (1.f / d) : 0.f;  // guard fully-masked columns
    float4* hp = (float4*)g_h;
    float4 v = hp[idx];
    v.x = __uint_as_float(f2tf32(v.x * inv));
    v.y = __uint_as_float(f2tf32(v.y * inv));
    v.z = __uint_as_float(f2tf32(v.z * inv));
    v.w = __uint_as_float(f2tf32(v.w * inv));
    hp[idx] = v;
    if ((idx & 31) == 0) {
        g_js[row] = make_float4(g_s2p[row], g_u2[row], g_v2[row], 0.f);
    }
}

// ---------------- kernel 4: out = relu(P @ h2), register-afr, triple-buffered ----------------
// grid (32, 8): x = 64-row i-block, y = batch. 512 thr = 16 warps: 4(M=16) x 4(N=32).
// One __syncthreads per k-tile (triple buffer: tile kt+2 written into the buffer last read
// at kt-1; the top-of-loop barrier orders it). Last tile peeled with wait_group 0.

__device__ __forceinline__ void attn_tile(const float* __restrict__ H,
                                          const float4* __restrict__ J,
                                          unsigned mwA, unsigned mwB,
                                          float s1A, float u1A, float v1A,
                                          float s1B, float u1B, float v1B,
                                          int wn, int r, int c, float acc[4][4]) {
#pragma unroll
    for (int ks = 0; ks < 4; ks++) {
        const int bp = ks * 8 + c;
        float4 ja = J[bp];
        float4 jb2 = J[bp + 4];
        unsigned afr[4];
        {
            float tt = s1A + ja.x;
            float p = (tt > 0.f) ? u1A * ja.y : v1A * ja.z;
            afr[0] = f2tf32(((mwA >> bp) & 1u) ? p : 0.f);
        }
        {
            float tt = s1B + ja.x;
            float p = (tt > 0.f) ? u1B * ja.y : v1B * ja.z;
            afr[1] = f2tf32(((mwB >> bp) & 1u) ? p : 0.f);
        }
        {
            float tt = s1A + jb2.x;
            float p = (tt > 0.f) ? u1A * jb2.y : v1A * jb2.z;
            afr[2] = f2tf32(((mwA >> (bp + 4)) & 1u) ? p : 0.f);
        }
        {
            float tt = s1B + jb2.x;
            float p = (tt > 0.f) ? u1B * jb2.y : v1B * jb2.z;
            afr[3] = f2tf32(((mwB >> (bp + 4)) & 1u) ? p : 0.f);
        }
#pragma unroll
        for (int nt = 0; nt < 4; nt++) {
            const int col = wn * 32 + nt * 8 + r;
            unsigned bb[2];
            bb[0] = __float_as_uint(H[bp * 136 + col]);
            bb[1] = __float_as_uint(H[(bp + 4) * 136 + col]);
            mma_tf32(acc[nt], afr, bb);
        }
    }
}

__global__ __launch_bounds__(512, 2) void k_attn(float* __restrict__ out) {
    extern __shared__ float smraw[];
    float* hs = smraw;                               // 3 x [32][136] = 52224 B
    float4* jstage = (float4*)(smraw + 3 * 32 * 136);  // 3 x [32] float4 = 1536 B

    const int b = blockIdx.y;
    const int i0 = blockIdx.x * 64;
    const int t = threadIdx.x;
    const int lane = t & 31, wid = t >> 5;
    const int wm = wid & 3, wn = wid >> 2;
    const int r = lane >> 2, c = lane & 3;
    const int nb = b * NN;

    const int rA = i0 + wm * 16 + r, rB = rA + 8;  // local row indices within batch
    const float s1A = g_s1[nb + rA], u1A = g_u1[nb + rA], v1A = g_v1[nb + rA];
    const float s1B = g_s1[nb + rB], u1B = g_u1[nb + rB], v1B = g_v1[nb + rB];
    const unsigned* mbase = g_maskT + (size_t)b * 64 * NN;  // word kt at mbase[kt*NN + row]

    const float* hsrc = g_h + (size_t)nb * FF;
    const float4* jsrc = g_js + nb;

    // cp.async mapping: 1024 16B chunks of Hs; each thread does 2. jstage: threads 0-31.
    const int r0 = t >> 5, c0 = (t & 31) * 4;
    const int r1 = (t + 512) >> 5, c1 = ((t + 512) & 31) * 4;
    const float* hsrc0 = hsrc + (size_t)r0 * FF + c0;
    const float* hsrc1 = hsrc + (size_t)r1 * FF + c1;
    unsigned hd0 = (unsigned)__cvta_generic_to_shared(hs + r0 * 136 + c0);
    unsigned hd1 = (unsigned)__cvta_generic_to_shared(hs + r1 * 136 + c1);
    unsigned jd = (unsigned)__cvta_generic_to_shared(jstage + (t & 31));

    float acc[4][4];
#pragma unroll
    for (int nt = 0; nt < 4; nt++)
#pragma unroll
        for (int q = 0; q < 4; q++) acc[nt][q] = 0.f;

    // prologue: prefetch tiles 0 and 1 into buffers 0 and 1
#pragma unroll
    for (int p = 0; p < 2; p++) {
        CP_ASYNC16(hd0 + p * 4352 * 4, hsrc0 + (size_t)p * 32 * FF);
        CP_ASYNC16(hd1 + p * 4352 * 4, hsrc1 + (size_t)p * 32 * FF);
        if (t < 32) CP_ASYNC16(jd + p * 512, jsrc + p * 32 + t);
        CP_COMMIT();
    }

    unsigned mwA = mbase[rA], mwB = mbase[rB];  // word 0

    // prefetch source pointers for tile kt+2 (start at tile 2)
    const float* pf0 = hsrc0 + (size_t)2 * 32 * FF;
    const float* pf1 = hsrc1 + (size_t)2 * 32 * FF;
    const float4* pfj = jsrc + 2 * 32 + (t & 31);

    int cur = 0;  // kt % 3
    int pre = 2;  // (kt+2) % 3
    for (int kt = 0; kt < 63; kt++) {
        CP_WAIT(1);  // tile kt's group complete (groups retire in order)
        __syncthreads();

        if (kt < 62) {  // prefetch tile kt+2 into buffer pre (last read at kt-1)
            CP_ASYNC16(hd0 + pre * 4352 * 4, pf0);
            CP_ASYNC16(hd1 + pre * 4352 * 4, pf1);
            if (t < 32) CP_ASYNC16(jd + pre * 512, pfj);
            CP_COMMIT();
            pf0 += 32 * FF;
            pf1 += 32 * FF;
            pfj += 32;
        }
        // mask words for next tile (prefetch into regs; hides LDG latency)
        unsigned mwA_n = mbase[(size_t)(kt + 1) * NN + rA];
        unsigned mwB_n = mbase[(size_t)(kt + 1) * NN + rB];

        attn_tile(hs + cur * 4352, jstage + cur * 32, mwA, mwB,
                  s1A, u1A, v1A, s1B, u1B, v1B, wn, r, c, acc);

        mwA = mwA_n;
        mwB = mwB_n;
        cur = (cur == 2) ? 0 : cur + 1;
        pre = (pre == 2) ? 0 : pre + 1;
    }
    // peeled last tile (kt = 63, buffer cur == 0)
    CP_WAIT(0);
    __syncthreads();
    attn_tile(hs + cur * 4352, jstage + cur * 32, mwA, mwB,
              s1A, u1A, v1A, s1B, u1B, v1B, wn, r, c, acc);

#pragma unroll
    for (int nt = 0; nt < 4; nt++) {
        int col = wn * 32 + nt * 8 + 2 * c;
        float2 o0 = {fmaxf(acc[nt][0], 0.f), fmaxf(acc[nt][1], 0.f)};
        float2 o1 = {fmaxf(acc[nt][2], 0.f), fmaxf(acc[nt][3], 0.f)};
        *(float2*)&out[(size_t)(nb + rA) * FF + col] = o0;
        *(float2*)&out[(size_t)(nb + rB) * FF + col] = o1;
    }
}

// ---------------- launch ----------------
extern "C" void kernel_launch(void* const* d_in, const int* in_sizes, int n_in,
                              void* d_out, int out_size) {
    const float* x = (const float*)d_in[0];
    const int* adj = (const int*)d_in[1];
    const float* W = (const float*)d_in[2];
    const float* bW = (const float*)d_in[3];
    const float* a1 = (const float*)d_in[4];
    const float* a2 = (const float*)d_in[5];
    const float* ba = (const float*)d_in[6];
    float* out = (float*)d_out;

    const int smem_attn = 3 * 32 * 136 * 4 + 3 * 32 * 16;  // 52224 + 1536 = 53760 B
    static bool attr_set = false;
    if (!attr_set) {
        cudaFuncSetAttribute(k_attn, cudaFuncAttributeMaxDynamicSharedMemorySize, smem_attn);
        attr_set = true;
    }

    k_gemm_h<<<256, 256>>>(x, W, bW, a1, a2, ba);
    k_pack<<<dim3(4, 32, 8), 128>>>(adj);
    k_scale<<<2048, 256>>>();
    k_attn<<<dim3(32, 8), 512, smem_attn>>>(out);
}

// round 14
// speedup vs baseline: 1.4556x; 1.1504x over previous
#include <cuda_runtime.h>
#include <cuda_fp16.h>
#include <cstdint>

#define BATCH 8
#define NN 2048
#define FF 128

// ---------------- scratch (static device globals; no allocation) ----------------
__device__ float g_h[BATCH * NN * FF];                 // h (fp32)
__device__ __half g_h2h[BATCH * FF * NN];              // half(h/D) TRANSPOSED [b][f][j]
__device__ float g_s1[BATCH * NN], g_s2p[BATCH * NN];  // s1, s2 + b_a
__device__ float g_u1[BATCH * NN], g_u2[BATCH * NN];   // exp(s1), exp(s2p)
__device__ float g_v1[BATCH * NN], g_v2[BATCH * NN];   // exp(0.2 s1), exp(0.2 s2p)
__device__ float g_DU[BATCH * NN], g_DV[BATCH * NN];   // column partial sums
__device__ float4 g_js[BATCH * NN];                    // packed j-stats (s2p, u2, v2, 0)
__device__ unsigned g_maskT[BATCH * (NN / 32) * NN];   // adjacency bitmask TRANSPOSED [b][word][i]

__device__ __forceinline__ unsigned pack_h2(float lo, float hi) {
    unsigned u;
    asm("cvt.rn.f16x2.f32 %0, %1, %2;" : "=r"(u) : "f"(hi), "f"(lo));
    return u;
}

__device__ __forceinline__ void mma_fp16(float* d, const unsigned* a, unsigned b0, unsigned b1) {
    asm volatile(
        "mma.sync.aligned.m16n8k16.row.col.f32.f16.f16.f32 "
        "{%0,%1,%2,%3}, {%4,%5,%6,%7}, {%8,%9}, {%0,%1,%2,%3};\n"
        : "+f"(d[0]), "+f"(d[1]), "+f"(d[2]), "+f"(d[3])
        : "r"(a[0]), "r"(a[1]), "r"(a[2]), "r"(a[3]), "r"(b0), "r"(b1));
}

#define CP_ASYNC16(dst, src) \
    asm volatile("cp.async.cg.shared.global [%0], [%1], 16;\n" ::"r"(dst), "l"(src))
#define CP_COMMIT() asm volatile("cp.async.commit_group;\n")
#define CP_WAIT(n) asm volatile("cp.async.wait_group %0;\n" ::"n"(n))

// ---------------- kernel 1: h = x @ W + b_W, fused row stats + DU/DV zero + g_js ----------------
__global__ __launch_bounds__(256) void k_gemm_h(const float* __restrict__ x,
                                                const float* __restrict__ W,
                                                const float* __restrict__ bW,
                                                const float* __restrict__ a1,
                                                const float* __restrict__ a2,
                                                const float* __restrict__ ba) {
    __shared__ float XsT[32][68];
    __shared__ float Ws[32][128];
    const int t = threadIdx.x;
    const int tx = t & 15, ty = t >> 4;
    const int m0 = blockIdx.x * 64;

    if (t < 64) {
        g_DU[m0 + t] = 0.f;
        g_DV[m0 + t] = 0.f;
    }

    float acc[4][8];
#pragma unroll
    for (int i = 0; i < 4; i++)
#pragma unroll
        for (int j = 0; j < 8; j++) acc[i][j] = 0.f;

    for (int k0 = 0; k0 < 128; k0 += 32) {
#pragma unroll
        for (int it = 0; it < 2; it++) {
            int q = t + it * 256;
            int rr = q >> 3, c4 = q & 7;
            float4 v = *(const float4*)&x[(m0 + rr) * 128 + k0 + c4 * 4];
            XsT[c4 * 4 + 0][rr] = v.x;
            XsT[c4 * 4 + 1][rr] = v.y;
            XsT[c4 * 4 + 2][rr] = v.z;
            XsT[c4 * 4 + 3][rr] = v.w;
        }
#pragma unroll
        for (int it = 0; it < 4; it++) {
            int q = t + it * 256;
            int rr = q >> 5, c4 = q & 31;
            *(float4*)&Ws[rr][c4 * 4] = *(const float4*)&W[(k0 + rr) * 128 + c4 * 4];
        }
        __syncthreads();
#pragma unroll
        for (int kk = 0; kk < 32; kk++) {
            float4 a = *(float4*)&XsT[kk][ty * 4];
            float4 b0 = *(float4*)&Ws[kk][tx * 4];
            float4 b1 = *(float4*)&Ws[kk][64 + tx * 4];
            float aa[4] = {a.x, a.y, a.z, a.w};
            float bb[8] = {b0.x, b0.y, b0.z, b0.w, b1.x, b1.y, b1.z, b1.w};
#pragma unroll
            for (int i = 0; i < 4; i++)
#pragma unroll
                for (int j = 0; j < 8; j++) acc[i][j] = fmaf(aa[i], bb[j], acc[i][j]);
        }
        __syncthreads();
    }

    float4 bwA = *(const float4*)&bW[tx * 4];
    float4 bwB = *(const float4*)&bW[64 + tx * 4];
    float4 a1A = *(const float4*)&a1[tx * 4];
    float4 a1B = *(const float4*)&a1[64 + tx * 4];
    float4 a2A = *(const float4*)&a2[tx * 4];
    float4 a2B = *(const float4*)&a2[64 + tx * 4];

    float p1[4], p2[4];
#pragma unroll
    for (int i = 0; i < 4; i++) {
        int row = m0 + ty * 4 + i;
        float4 o0 = {acc[i][0] + bwA.x, acc[i][1] + bwA.y, acc[i][2] + bwA.z, acc[i][3] + bwA.w};
        float4 o1 = {acc[i][4] + bwB.x, acc[i][5] + bwB.y, acc[i][6] + bwB.z, acc[i][7] + bwB.w};
        *(float4*)&g_h[row * 128 + tx * 4] = o0;
        *(float4*)&g_h[row * 128 + 64 + tx * 4] = o1;
        p1[i] = o0.x * a1A.x + o0.y * a1A.y + o0.z * a1A.z + o0.w * a1A.w +
                o1.x * a1B.x + o1.y * a1B.y + o1.z * a1B.z + o1.w * a1B.w;
        p2[i] = o0.x * a2A.x + o0.y * a2A.y + o0.z * a2A.z + o0.w * a2A.w +
                o1.x * a2B.x + o1.y * a2B.y + o1.z * a2B.z + o1.w * a2B.w;
    }
#pragma unroll
    for (int off = 8; off > 0; off >>= 1) {
#pragma unroll
        for (int i = 0; i < 4; i++) {
            p1[i] += __shfl_down_sync(0xffffffffu, p1[i], off);
            p2[i] += __shfl_down_sync(0xffffffffu, p2[i], off);
        }
    }
    if (tx == 0) {
        float ba0 = ba[0];
#pragma unroll
        for (int i = 0; i < 4; i++) {
            int row = m0 + ty * 4 + i;
            float s1v = p1[i];
            float s2pv = p2[i] + ba0;
            float u2v = expf(s2pv), v2v = expf(0.2f * s2pv);
            g_s1[row] = s1v;
            g_s2p[row] = s2pv;
            g_u1[row] = expf(s1v);
            g_u2[row] = u2v;
            g_v1[row] = expf(0.2f * s1v);
            g_v2[row] = v2v;
            g_js[row] = make_float4(s2pv, u2v, v2v, 0.f);
        }
    }
}

// ---------------- kernel 2: fused adj pack (transposed bitmask) + column sums ----------------
// grid (4, 32, 8): x = 512-col block, y = 64-row chunk, z = batch. 128 thr, 4 cols/thread.
__global__ __launch_bounds__(128) void k_pack(const int* __restrict__ adj) {
    const int t = threadIdx.x;
    const int jb = blockIdx.x, ic = blockIdx.y, b = blockIdx.z;
    const int i0 = ic * 64;
    const int nb = b * NN;
    __shared__ float s1s[64], u1s[64], v1s[64];
    if (t < 64) {
        s1s[t] = g_s1[nb + i0 + t];
        u1s[t] = g_u1[nb + i0 + t];
        v1s[t] = g_v1[nb + i0 + t];
    }
    __syncthreads();

    const int jloc = jb * 512 + t * 4;
    const int sub = t & 7;
    float s2p[4], accU[4], accV[4];
#pragma unroll
    for (int q = 0; q < 4; q++) {
        s2p[q] = g_s2p[nb + jloc + q];
        accU[q] = 0.f;
        accV[q] = 0.f;
    }
    const int4* arow = (const int4*)(adj + (size_t)b * NN * NN + (size_t)i0 * NN + jb * 512);
    unsigned* mcol = g_maskT + ((size_t)b * 64 + jb * 16 + (t >> 3)) * NN + i0;
    const int stride4 = NN / 4;

#pragma unroll 4
    for (int ii = 0; ii < 64; ii++) {
        int4 av = arow[ii * stride4 + t];
        bool m0 = av.x > 0, m1 = av.y > 0, m2 = av.z > 0, m3 = av.w > 0;
        unsigned nib = (m0 ? 1u : 0u) | (m1 ? 2u : 0u) | (m2 ? 4u : 0u) | (m3 ? 8u : 0u);
        unsigned w = nib << (sub * 4);
        w |= __shfl_xor_sync(0xffffffffu, w, 1);
        w |= __shfl_xor_sync(0xffffffffu, w, 2);
        w |= __shfl_xor_sync(0xffffffffu, w, 4);
        if (sub == 0) mcol[ii] = w;

        float s1i = s1s[ii], u1i = u1s[ii], v1i = v1s[ii];
        bool mm[4] = {m0, m1, m2, m3};
#pragma unroll
        for (int q = 0; q < 4; q++) {
            float tt = s1i + s2p[q];
            accU[q] += (mm[q] && tt > 0.f) ? u1i : 0.f;
            accV[q] += (mm[q] && tt <= 0.f) ? v1i : 0.f;
        }
    }
#pragma unroll
    for (int q = 0; q < 4; q++) {
        atomicAdd(&g_DU[nb + jloc + q], accU[q]);
        atomicAdd(&g_DV[nb + jloc + q], accV[q]);
    }
}

// ---------------- kernel 3: h2h[b][f][j] = half(h[b][j][f] / D[b][j])  (transpose) ----------------
// grid (64, 4, 8), block (32, 8): 32x32 tiles.
__global__ __launch_bounds__(256) void k_scaleT() {
    __shared__ float tile[32][33];
    const int b = blockIdx.z;
    const int j0 = blockIdx.x * 32, f0 = blockIdx.y * 32;
    const int tx = threadIdx.x, ty = threadIdx.y;
    const int nb = b * NN;
#pragma unroll
    for (int q = 0; q < 4; q++) {
        int j = j0 + ty + q * 8;
        tile[ty + q * 8][tx] = g_h[(size_t)(nb + j) * FF + f0 + tx];
    }
    __syncthreads();
    int jj = nb + j0 + tx;
    float d = g_u2[jj] * g_DU[jj] + g_v2[jj] * g_DV[jj];
    float inv = (d != 0.f) ? (1.f / d) : 0.f;  // guard fully-masked columns
#pragma unroll
    for (int q = 0; q < 4; q++) {
        int f = f0 + ty + q * 8;
        g_h2h[((size_t)b * FF + f) * NN + j0 + tx] = __float2half_rn(tile[tx][ty + q * 8] * inv);
    }
}

// ---------------- kernel 4: out = relu(P @ h2), fp16 m16n8k16, triple-buffered ----------------
// grid (32, 8): 64-row i-block, batch. 512 thr = 16 warps: 4(M=16) x 4(N=32).
// Hs: [f=128][k=32] half, stride 40 halfs (80 B) -> B-frag LDS banks (20r+c)%32 all distinct.
#define HT_HALFS (128 * 40)
#define HT_BYTES (HT_HALFS * 2)  // 10240

__device__ __forceinline__ void attn_tile(const __half* __restrict__ H,
                                          const float4* __restrict__ J,
                                          unsigned mwA, unsigned mwB,
                                          float s1A, float u1A, float v1A,
                                          float s1B, float u1B, float v1B,
                                          int wn, int r, int c, float acc[4][4]) {
#pragma unroll
    for (int s = 0; s < 2; s++) {
        const int j0 = s * 16 + 2 * c;
        const int jb_[4] = {j0, j0 + 1, j0 + 8, j0 + 9};
        float pA[4], pB[4];
#pragma unroll
        for (int q = 0; q < 4; q++) {
            float4 jv = J[jb_[q]];
            float tA = s1A + jv.x;
            float vA = (tA > 0.f) ? u1A * jv.y : v1A * jv.z;
            pA[q] = ((mwA >> jb_[q]) & 1u) ? vA : 0.f;
            float tB = s1B + jv.x;
            float vB = (tB > 0.f) ? u1B * jv.y : v1B * jv.z;
            pB[q] = ((mwB >> jb_[q]) & 1u) ? vB : 0.f;
        }
        unsigned afr[4];
        afr[0] = pack_h2(pA[0], pA[1]);  // row rA, k = 2c, 2c+1
        afr[1] = pack_h2(pB[0], pB[1]);  // row rB
        afr[2] = pack_h2(pA[2], pA[3]);  // row rA, k = 2c+8, 2c+9
        afr[3] = pack_h2(pB[2], pB[3]);
#pragma unroll
        for (int nt = 0; nt < 4; nt++) {
            const int f = wn * 32 + nt * 8 + r;
            unsigned b0 = *(const unsigned*)&H[f * 40 + s * 16 + 2 * c];
            unsigned b1 = *(const unsigned*)&H[f * 40 + s * 16 + 2 * c + 8];
            mma_fp16(acc[nt], afr, b0, b1);
        }
    }
}

__global__ __launch_bounds__(512, 2) void k_attn(float* __restrict__ out) {
    extern __shared__ char smraw[];
    __half* hs = (__half*)smraw;                       // 3 x HT_BYTES = 30720
    float4* jstage = (float4*)(smraw + 3 * HT_BYTES);  // 3 x [32] float4 = 1536

    const int b = blockIdx.y;
    const int i0 = blockIdx.x * 64;
    const int t = threadIdx.x;
    const int lane = t & 31, wid = t >> 5;
    const int wm = wid & 3, wn = wid >> 2;
    const int r = lane >> 2, c = lane & 3;
    const int nb = b * NN;

    const int rA = i0 + wm * 16 + r, rB = rA + 8;
    const float s1A = g_s1[nb + rA], u1A = g_u1[nb + rA], v1A = g_v1[nb + rA];
    const float s1B = g_s1[nb + rB], u1B = g_u1[nb + rB], v1B = g_v1[nb + rB];
    const unsigned* mbase = g_maskT + (size_t)b * 64 * NN;

    const float4* jsrc = g_js + nb;

    // cp.async mapping: 512 16B chunks of the half tile; 1 per thread.
    const int fr = t >> 2, ci = t & 3;
    const __half* hsrc = g_h2h + ((size_t)b * FF + fr) * NN + ci * 8;  // + kt*32 per tile
    unsigned hd = (unsigned)__cvta_generic_to_shared(hs + fr * 40 + ci * 8);
    unsigned jd = (unsigned)__cvta_generic_to_shared(jstage + (t & 31));

    float acc[4][4];
#pragma unroll
    for (int nt = 0; nt < 4; nt++)
#pragma unroll
        for (int q = 0; q < 4; q++) acc[nt][q] = 0.f;

    // prologue: prefetch tiles 0 and 1 into buffers 0 and 1
#pragma unroll
    for (int p = 0; p < 2; p++) {
        CP_ASYNC16(hd + p * HT_BYTES, hsrc + p * 32);
        if (t < 32) CP_ASYNC16(jd + p * 512, jsrc + p * 32 + t);
        CP_COMMIT();
    }

    unsigned mwA = mbase[rA], mwB = mbase[rB];  // word 0

    const __half* pf = hsrc + 2 * 32;
    const float4* pfj = jsrc + 2 * 32 + (t & 31);

    int cur = 0, pre = 2;
    for (int kt = 0; kt < 63; kt++) {
        CP_WAIT(1);
        __syncthreads();

        if (kt < 62) {
            CP_ASYNC16(hd + pre * HT_BYTES, pf);
            if (t < 32) CP_ASYNC16(jd + pre * 512, pfj);
            CP_COMMIT();
            pf += 32;
            pfj += 32;
        }
        unsigned mwA_n = mbase[(size_t)(kt + 1) * NN + rA];
        unsigned mwB_n = mbase[(size_t)(kt + 1) * NN + rB];

        attn_tile(hs + cur * HT_HALFS, jstage + cur * 32, mwA, mwB,
                  s1A, u1A, v1A, s1B, u1B, v1B, wn, r, c, acc);

        mwA = mwA_n;
        mwB = mwB_n;
        cur = (cur == 2) ? 0 : cur + 1;
        pre = (pre == 2) ? 0 : pre + 1;
    }
    CP_WAIT(0);
    __syncthreads();
    attn_tile(hs + cur * HT_HALFS, jstage + cur * 32, mwA, mwB,
              s1A, u1A, v1A, s1B, u1B, v1B, wn, r, c, acc);

#pragma unroll
    for (int nt = 0; nt < 4; nt++) {
        int col = wn * 32 + nt * 8 + 2 * c;
        float2 o0 = {fmaxf(acc[nt][0], 0.f), fmaxf(acc[nt][1], 0.f)};
        float2 o1 = {fmaxf(acc[nt][2], 0.f), fmaxf(acc[nt][3], 0.f)};
        *(float2*)&out[(size_t)(nb + rA) * FF + col] = o0;
        *(float2*)&out[(size_t)(nb + rB) * FF + col] = o1;
    }
}

// ---------------- launch ----------------
extern "C" void kernel_launch(void* const* d_in, const int* in_sizes, int n_in,
                              void* d_out, int out_size) {
    const float* x = (const float*)d_in[0];
    const int* adj = (const int*)d_in[1];
    const float* W = (const float*)d_in[2];
    const float* bW = (const float*)d_in[3];
    const float* a1 = (const float*)d_in[4];
    const float* a2 = (const float*)d_in[5];
    const float* ba = (const float*)d_in[6];
    float* out = (float*)d_out;

    const int smem_attn = 3 * HT_BYTES + 3 * 32 * 16;  // 30720 + 1536 = 32256 B
    static bool attr_set = false;
    if (!attr_set) {
        cudaFuncSetAttribute(k_attn, cudaFuncAttributeMaxDynamicSharedMemorySize, smem_attn);
        attr_set = true;
    }

    k_gemm_h<<<256, 256>>>(x, W, bW, a1, a2, ba);
    k_pack<<<dim3(4, 32, 8), 128>>>(adj);
    k_scaleT<<<dim3(64, 4, 8), dim3(32, 8)>>>();
    k_attn<<<dim3(32, 8), 512, smem_attn>>>(out);
}

// round 16
// speedup vs baseline: 1.7622x; 1.2106x over previous
#include <cuda_runtime.h>
#include <cuda_fp16.h>
#include <cstdint>

#define BATCH 8
#define NN 2048
#define FF 128

// ---------------- scratch (static device globals; no allocation) ----------------
__device__ float g_h[BATCH * NN * FF];                 // h (fp32)
__device__ __half g_h2h[BATCH * FF * NN];              // half(h/D) TRANSPOSED [b][f][j]
__device__ __half g_Ph[(size_t)BATCH * NN * NN];       // P numerator half [b][i][j]
__device__ float g_s1[BATCH * NN], g_s2p[BATCH * NN];  // s1, s2 + b_a
__device__ float g_u1[BATCH * NN], g_u2[BATCH * NN];   // exp(s1), exp(s2p)
__device__ float g_v1[BATCH * NN], g_v2[BATCH * NN];   // exp(0.2 s1), exp(0.2 s2p)
__device__ float g_D[BATCH * NN];                      // column sums of P

__device__ __forceinline__ unsigned pack_h2(float lo, float hi) {
    unsigned u;
    asm("cvt.rn.f16x2.f32 %0, %1, %2;" : "=r"(u) : "f"(hi), "f"(lo));
    return u;
}

__device__ __forceinline__ void mma_fp16(float* d, unsigned a0, unsigned a1, unsigned a2,
                                         unsigned a3, unsigned b0, unsigned b1) {
    asm volatile(
        "mma.sync.aligned.m16n8k16.row.col.f32.f16.f16.f32 "
        "{%0,%1,%2,%3}, {%4,%5,%6,%7}, {%8,%9}, {%0,%1,%2,%3};\n"
        : "+f"(d[0]), "+f"(d[1]), "+f"(d[2]), "+f"(d[3])
        : "r"(a0), "r"(a1), "r"(a2), "r"(a3), "r"(b0), "r"(b1));
}

__device__ __forceinline__ void ldsm_x4(unsigned& r0, unsigned& r1, unsigned& r2, unsigned& r3,
                                        uint32_t addr) {
    asm volatile("ldmatrix.sync.aligned.m8n8.x4.shared.b16 {%0,%1,%2,%3}, [%4];"
                 : "=r"(r0), "=r"(r1), "=r"(r2), "=r"(r3)
                 : "r"(addr));
}

#define CP_ASYNC16(dst, src) \
    asm volatile("cp.async.cg.shared.global [%0], [%1], 16;\n" ::"r"(dst), "l"(src))
#define CP_COMMIT() asm volatile("cp.async.commit_group;\n")
#define CP_WAIT(n) asm volatile("cp.async.wait_group %0;\n" ::"n"(n))

// ---------------- kernel 1: h = x @ W + b_W, fused row stats + D zeroing ----------------
__global__ __launch_bounds__(256) void k_gemm_h(const float* __restrict__ x,
                                                const float* __restrict__ W,
                                                const float* __restrict__ bW,
                                                const float* __restrict__ a1,
                                                const float* __restrict__ a2,
                                                const float* __restrict__ ba) {
    __shared__ float XsT[32][68];
    __shared__ float Ws[32][128];
    const int t = threadIdx.x;
    const int tx = t & 15, ty = t >> 4;
    const int m0 = blockIdx.x * 64;

    if (t < 64) g_D[m0 + t] = 0.f;

    float acc[4][8];
#pragma unroll
    for (int i = 0; i < 4; i++)
#pragma unroll
        for (int j = 0; j < 8; j++) acc[i][j] = 0.f;

    for (int k0 = 0; k0 < 128; k0 += 32) {
#pragma unroll
        for (int it = 0; it < 2; it++) {
            int q = t + it * 256;
            int rr = q >> 3, c4 = q & 7;
            float4 v = *(const float4*)&x[(m0 + rr) * 128 + k0 + c4 * 4];
            XsT[c4 * 4 + 0][rr] = v.x;
            XsT[c4 * 4 + 1][rr] = v.y;
            XsT[c4 * 4 + 2][rr] = v.z;
            XsT[c4 * 4 + 3][rr] = v.w;
        }
#pragma unroll
        for (int it = 0; it < 4; it++) {
            int q = t + it * 256;
            int rr = q >> 5, c4 = q & 31;
            *(float4*)&Ws[rr][c4 * 4] = *(const float4*)&W[(k0 + rr) * 128 + c4 * 4];
        }
        __syncthreads();
#pragma unroll
        for (int kk = 0; kk < 32; kk++) {
            float4 a = *(float4*)&XsT[kk][ty * 4];
            float4 b0 = *(float4*)&Ws[kk][tx * 4];
            float4 b1 = *(float4*)&Ws[kk][64 + tx * 4];
            float aa[4] = {a.x, a.y, a.z, a.w};
            float bb[8] = {b0.x, b0.y, b0.z, b0.w, b1.x, b1.y, b1.z, b1.w};
#pragma unroll
            for (int i = 0; i < 4; i++)
#pragma unroll
                for (int j = 0; j < 8; j++) acc[i][j] = fmaf(aa[i], bb[j], acc[i][j]);
        }
        __syncthreads();
    }

    float4 bwA = *(const float4*)&bW[tx * 4];
    float4 bwB = *(const float4*)&bW[64 + tx * 4];
    float4 a1A = *(const float4*)&a1[tx * 4];
    float4 a1B = *(const float4*)&a1[64 + tx * 4];
    float4 a2A = *(const float4*)&a2[tx * 4];
    float4 a2B = *(const float4*)&a2[64 + tx * 4];

    float p1[4], p2[4];
#pragma unroll
    for (int i = 0; i < 4; i++) {
        int row = m0 + ty * 4 + i;
        float4 o0 = {acc[i][0] + bwA.x, acc[i][1] + bwA.y, acc[i][2] + bwA.z, acc[i][3] + bwA.w};
        float4 o1 = {acc[i][4] + bwB.x, acc[i][5] + bwB.y, acc[i][6] + bwB.z, acc[i][7] + bwB.w};
        *(float4*)&g_h[row * 128 + tx * 4] = o0;
        *(float4*)&g_h[row * 128 + 64 + tx * 4] = o1;
        p1[i] = o0.x * a1A.x + o0.y * a1A.y + o0.z * a1A.z + o0.w * a1A.w +
                o1.x * a1B.x + o1.y * a1B.y + o1.z * a1B.z + o1.w * a1B.w;
        p2[i] = o0.x * a2A.x + o0.y * a2A.y + o0.z * a2A.z + o0.w * a2A.w +
                o1.x * a2B.x + o1.y * a2B.y + o1.z * a2B.z + o1.w * a2B.w;
    }
#pragma unroll
    for (int off = 8; off > 0; off >>= 1) {
#pragma unroll
        for (int i = 0; i < 4; i++) {
            p1[i] += __shfl_down_sync(0xffffffffu, p1[i], off);
            p2[i] += __shfl_down_sync(0xffffffffu, p2[i], off);
        }
    }
    if (tx == 0) {
        float ba0 = ba[0];
#pragma unroll
        for (int i = 0; i < 4; i++) {
            int row = m0 + ty * 4 + i;
            float s1v = p1[i];
            float s2pv = p2[i] + ba0;
            g_s1[row] = s1v;
            g_s2p[row] = s2pv;
            g_u1[row] = expf(s1v);
            g_u2[row] = expf(s2pv);
            g_v1[row] = expf(0.2f * s1v);
            g_v2[row] = expf(0.2f * s2pv);
        }
    }
}

// ---------------- kernel 2: adj -> P (half, gmem) + column sums D ----------------
// grid (4, 32, 8): x = 512-col block, y = 64-row chunk, z = batch. 128 thr, 4 cols/thread.
__global__ __launch_bounds__(128) void k_pack(const int* __restrict__ adj) {
    const int t = threadIdx.x;
    const int jb = blockIdx.x, ic = blockIdx.y, b = blockIdx.z;
    const int i0 = ic * 64;
    const int nb = b * NN;
    __shared__ float s1s[64], u1s[64], v1s[64];
    if (t < 64) {
        s1s[t] = g_s1[nb + i0 + t];
        u1s[t] = g_u1[nb + i0 + t];
        v1s[t] = g_v1[nb + i0 + t];
    }
    __syncthreads();

    const int jloc = jb * 512 + t * 4;
    float s2p[4], u2j[4], v2j[4], accD[4];
#pragma unroll
    for (int q = 0; q < 4; q++) {
        s2p[q] = g_s2p[nb + jloc + q];
        u2j[q] = g_u2[nb + jloc + q];
        v2j[q] = g_v2[nb + jloc + q];
        accD[q] = 0.f;
    }
    const int4* arow = (const int4*)(adj + (size_t)b * NN * NN + (size_t)i0 * NN + jb * 512);
    __half* pbase = g_Ph + (size_t)(nb + i0) * NN + jloc;
    const int stride4 = NN / 4;

#pragma unroll 4
    for (int ii = 0; ii < 64; ii++) {
        int4 av = arow[ii * stride4 + t];
        float s1i = s1s[ii], u1i = u1s[ii], v1i = v1s[ii];
        int e[4] = {av.x, av.y, av.z, av.w};
        float p[4];
#pragma unroll
        for (int q = 0; q < 4; q++) {
            float tt = s1i + s2p[q];
            float pv = (tt > 0.f) ? u1i * u2j[q] : v1i * v2j[q];
            pv = (e[q] > 0) ? pv : 0.f;
            accD[q] += pv;
            p[q] = pv;
        }
        uint2 st;
        st.x = pack_h2(p[0], p[1]);
        st.y = pack_h2(p[2], p[3]);
        *(uint2*)(pbase + (size_t)ii * NN) = st;
    }
#pragma unroll
    for (int q = 0; q < 4; q++) atomicAdd(&g_D[nb + jloc + q], accD[q]);
}

// ---------------- kernel 3: h2h[b][f][j] = half(h[b][j][f] / D[b][j]) (transpose) ----------------
// grid (64, 4, 8), block (32, 8): 32x32 tiles.
__global__ __launch_bounds__(256) void k_scaleT() {
    __shared__ float tile[32][33];
    const int b = blockIdx.z;
    const int j0 = blockIdx.x * 32, f0 = blockIdx.y * 32;
    const int tx = threadIdx.x, ty = threadIdx.y;
    const int nb = b * NN;
#pragma unroll
    for (int q = 0; q < 4; q++) {
        int j = j0 + ty + q * 8;
        tile[ty + q * 8][tx] = g_h[(size_t)(nb + j) * FF + f0 + tx];
    }
    __syncthreads();
    float d = g_D[nb + j0 + tx];
    float inv = (d != 0.f) ? (1.f / d) : 0.f;  // guard fully-masked columns
#pragma unroll
    for (int q = 0; q < 4; q++) {
        int f = f0 + ty + q * 8;
        g_h2h[((size_t)b * FF + f) * NN + j0 + tx] = __float2half_rn(tile[tx][ty + q * 8] * inv);
    }
}

// ---------------- kernel 4: out = relu(P @ h2), pure fp16 GEMM (ldmatrix + mma) ----------------
// grid (32, 8): 64-row i-block, batch. 512 thr = 16 warps: 4(M=16) x 4(N=32).
// Tiles stride 40 halfs (80 B): ldmatrix 16B-unit phase (r*5 mod 8 distinct) and B-frag LDS
// ((20r+c) mod 32 distinct) both conflict-free. Triple-buffered cp.async, 1 barrier/kt.
#define ASTRIDE 40
#define AT_BYTES (64 * ASTRIDE * 2)    // 5120
#define BT_BYTES (128 * ASTRIDE * 2)   // 10240

__device__ __forceinline__ void attn_tile(uint32_t aAddr, const __half* __restrict__ H,
                                          int wn, int r, int c, float acc[4][4]) {
#pragma unroll
    for (int s = 0; s < 2; s++) {
        unsigned a0, a1, a2, a3;
        ldsm_x4(a0, a1, a2, a3, aAddr + s * 32);  // +16 halfs per s
#pragma unroll
        for (int nt = 0; nt < 4; nt++) {
            const int f = wn * 32 + nt * 8 + r;
            unsigned b0 = *(const unsigned*)&H[f * ASTRIDE + s * 16 + 2 * c];
            unsigned b1 = *(const unsigned*)&H[f * ASTRIDE + s * 16 + 2 * c + 8];
            mma_fp16(acc[nt], a0, a1, a2, a3, b0, b1);
        }
    }
}

__global__ __launch_bounds__(512, 2) void k_attn(float* __restrict__ out) {
    extern __shared__ char smraw[];
    __half* As = (__half*)smraw;                        // 3 x AT_BYTES
    __half* Bs = (__half*)(smraw + 3 * AT_BYTES);       // 3 x BT_BYTES

    const int b = blockIdx.y;
    const int i0 = blockIdx.x * 64;
    const int t = threadIdx.x;
    const int lane = t & 31, wid = t >> 5;
    const int wm = wid & 3, wn = wid >> 2;
    const int r = lane >> 2, c = lane & 3;
    const int nb = b * NN;

    const __half* aSrc = g_Ph + (size_t)(nb + i0) * NN;
    const __half* bSrc = g_h2h + (size_t)b * FF * NN;

    // cp.async mapping: B = 512 chunks (all threads), A = 256 chunks (t < 256).
    const int brow = t >> 2, bseg = t & 3;
    const __half* bgp = bSrc + (size_t)brow * NN + bseg * 8;
    unsigned bdst = (unsigned)__cvta_generic_to_shared(Bs + brow * ASTRIDE + bseg * 8);
    const __half* agp = aSrc + (size_t)(t >> 2) * NN + (t & 3) * 8;
    unsigned adst = (unsigned)__cvta_generic_to_shared(As + (t >> 2) * ASTRIDE + (t & 3) * 8);

    // ldmatrix A-frag source addr (within buffer 0)
    uint32_t aAddr = (uint32_t)__cvta_generic_to_shared(
        As + (wm * 16 + (lane & 15)) * ASTRIDE + (lane >> 4) * 8);

    float acc[4][4];
#pragma unroll
    for (int nt = 0; nt < 4; nt++)
#pragma unroll
        for (int q = 0; q < 4; q++) acc[nt][q] = 0.f;

    // prologue: prefetch tiles 0 and 1
#pragma unroll
    for (int p = 0; p < 2; p++) {
        CP_ASYNC16(bdst + p * BT_BYTES, bgp + p * 32);
        if (t < 256) CP_ASYNC16(adst + p * AT_BYTES, agp + p * 32);
        CP_COMMIT();
    }

    const __half* pfB = bgp + 2 * 32;
    const __half* pfA = agp + 2 * 32;

    int cur = 0, pre = 2;
    for (int kt = 0; kt < 63; kt++) {
        CP_WAIT(1);
        __syncthreads();

        if (kt < 62) {
            CP_ASYNC16(bdst + pre * BT_BYTES, pfB);
            if (t < 256) CP_ASYNC16(adst + pre * AT_BYTES, pfA);
            CP_COMMIT();
            pfB += 32;
            pfA += 32;
        }

        attn_tile(aAddr + cur * AT_BYTES, Bs + cur * (BT_BYTES / 2), wn, r, c, acc);

        cur = (cur == 2) ? 0 : cur + 1;
        pre = (pre == 2) ? 0 : pre + 1;
    }
    CP_WAIT(0);
    __syncthreads();
    attn_tile(aAddr + cur * AT_BYTES, Bs + cur * (BT_BYTES / 2), wn, r, c, acc);

    const int rA = i0 + wm * 16 + r, rB = rA + 8;
#pragma unroll
    for (int nt = 0; nt < 4; nt++) {
        int col = wn * 32 + nt * 8 + 2 * c;
        float2 o0 = {fmaxf(acc[nt][0], 0.f), fmaxf(acc[nt][1], 0.f)};
        float2 o1 = {fmaxf(acc[nt][2], 0.f), fmaxf(acc[nt][3], 0.f)};
        *(float2*)&out[(size_t)(nb + rA) * FF + col] = o0;
        *(float2*)&out[(size_t)(nb + rB) * FF + col] = o1;
    }
}

// ---------------- launch ----------------
extern "C" void kernel_launch(void* const* d_in, const int* in_sizes, int n_in,
                              void* d_out, int out_size) {
    const float* x = (const float*)d_in[0];
    const int* adj = (const int*)d_in[1];
    const float* W = (const float*)d_in[2];
    const float* bW = (const float*)d_in[3];
    const float* a1 = (const float*)d_in[4];
    const float* a2 = (const float*)d_in[5];
    const float* ba = (const float*)d_in[6];
    float* out = (float*)d_out;

    const int smem_attn = 3 * (AT_BYTES + BT_BYTES);  // 46080 B
    static bool attr_set = false;
    if (!attr_set) {
        cudaFuncSetAttribute(k_attn, cudaFuncAttributeMaxDynamicSharedMemorySize, smem_attn);
        attr_set = true;
    }

    k_gemm_h<<<256, 256>>>(x, W, bW, a1, a2, ba);
    k_pack<<<dim3(4, 32, 8), 128>>>(adj);
    k_scaleT<<<dim3(64, 4, 8), dim3(32, 8)>>>();
    k_attn<<<dim3(32, 8), 512, smem_attn>>>(out);
}

// round 17
// speedup vs baseline: 2.0270x; 1.1502x over previous
#include <cuda_runtime.h>
#include <cuda_fp16.h>
#include <cstdint>

#define BATCH 8
#define NN 2048
#define FF 128

// ---------------- scratch (static device globals; no allocation) ----------------
__device__ float g_h[BATCH * NN * FF];                 // h (fp32)
__device__ __half g_h2h[BATCH * FF * NN];              // half(h/D) TRANSPOSED [b][f][j]
__device__ __half g_Ph[(size_t)BATCH * NN * NN];       // P numerator half [b][i][j]
__device__ float g_s1[BATCH * NN], g_s2p[BATCH * NN];  // s1, s2 + b_a
__device__ float g_u1[BATCH * NN], g_u2[BATCH * NN];   // exp(s1), exp(s2p)
__device__ float g_v1[BATCH * NN], g_v2[BATCH * NN];   // exp(0.2 s1), exp(0.2 s2p)
__device__ float g_D[BATCH * NN];                      // column sums of P

__device__ __forceinline__ unsigned pack_h2(float lo, float hi) {
    unsigned u;
    asm("cvt.rn.f16x2.f32 %0, %1, %2;" : "=r"(u) : "f"(hi), "f"(lo));
    return u;
}

__device__ __forceinline__ void mma_fp16(float* d, const unsigned* a, unsigned b0, unsigned b1) {
    asm volatile(
        "mma.sync.aligned.m16n8k16.row.col.f32.f16.f16.f32 "
        "{%0,%1,%2,%3}, {%4,%5,%6,%7}, {%8,%9}, {%0,%1,%2,%3};\n"
        : "+f"(d[0]), "+f"(d[1]), "+f"(d[2]), "+f"(d[3])
        : "r"(a[0]), "r"(a[1]), "r"(a[2]), "r"(a[3]), "r"(b0), "r"(b1));
}

__device__ __forceinline__ void ldsm_x4(unsigned* r, uint32_t addr) {
    asm volatile("ldmatrix.sync.aligned.m8n8.x4.shared.b16 {%0,%1,%2,%3}, [%4];"
                 : "=r"(r[0]), "=r"(r[1]), "=r"(r[2]), "=r"(r[3])
                 : "r"(addr));
}

#define CP_ASYNC16(dst, src) \
    asm volatile("cp.async.cg.shared.global [%0], [%1], 16;\n" ::"r"(dst), "l"(src))
#define CP_COMMIT() asm volatile("cp.async.commit_group;\n")
#define CP_WAIT(n) asm volatile("cp.async.wait_group %0;\n" ::"n"(n))

// ---------------- kernel 1: h = x @ W + b_W, fused row stats + D zeroing ----------------
__global__ __launch_bounds__(256) void k_gemm_h(const float* __restrict__ x,
                                                const float* __restrict__ W,
                                                const float* __restrict__ bW,
                                                const float* __restrict__ a1,
                                                const float* __restrict__ a2,
                                                const float* __restrict__ ba) {
    __shared__ float XsT[32][68];
    __shared__ float Ws[32][128];
    const int t = threadIdx.x;
    const int tx = t & 15, ty = t >> 4;
    const int m0 = blockIdx.x * 64;

    if (t < 64) g_D[m0 + t] = 0.f;

    float acc[4][8];
#pragma unroll
    for (int i = 0; i < 4; i++)
#pragma unroll
        for (int j = 0; j < 8; j++) acc[i][j] = 0.f;

    for (int k0 = 0; k0 < 128; k0 += 32) {
#pragma unroll
        for (int it = 0; it < 2; it++) {
            int q = t + it * 256;
            int rr = q >> 3, c4 = q & 7;
            float4 v = *(const float4*)&x[(m0 + rr) * 128 + k0 + c4 * 4];
            XsT[c4 * 4 + 0][rr] = v.x;
            XsT[c4 * 4 + 1][rr] = v.y;
            XsT[c4 * 4 + 2][rr] = v.z;
            XsT[c4 * 4 + 3][rr] = v.w;
        }
#pragma unroll
        for (int it = 0; it < 4; it++) {
            int q = t + it * 256;
            int rr = q >> 5, c4 = q & 31;
            *(float4*)&Ws[rr][c4 * 4] = *(const float4*)&W[(k0 + rr) * 128 + c4 * 4];
        }
        __syncthreads();
#pragma unroll
        for (int kk = 0; kk < 32; kk++) {
            float4 a = *(float4*)&XsT[kk][ty * 4];
            float4 b0 = *(float4*)&Ws[kk][tx * 4];
            float4 b1 = *(float4*)&Ws[kk][64 + tx * 4];
            float aa[4] = {a.x, a.y, a.z, a.w};
            float bb[8] = {b0.x, b0.y, b0.z, b0.w, b1.x, b1.y, b1.z, b1.w};
#pragma unroll
            for (int i = 0; i < 4; i++)
#pragma unroll
                for (int j = 0; j < 8; j++) acc[i][j] = fmaf(aa[i], bb[j], acc[i][j]);
        }
        __syncthreads();
    }

    float4 bwA = *(const float4*)&bW[tx * 4];
    float4 bwB = *(const float4*)&bW[64 + tx * 4];
    float4 a1A = *(const float4*)&a1[tx * 4];
    float4 a1B = *(const float4*)&a1[64 + tx * 4];
    float4 a2A = *(const float4*)&a2[tx * 4];
    float4 a2B = *(const float4*)&a2[64 + tx * 4];

    float p1[4], p2[4];
#pragma unroll
    for (int i = 0; i < 4; i++) {
        int row = m0 + ty * 4 + i;
        float4 o0 = {acc[i][0] + bwA.x, acc[i][1] + bwA.y, acc[i][2] + bwA.z, acc[i][3] + bwA.w};
        float4 o1 = {acc[i][4] + bwB.x, acc[i][5] + bwB.y, acc[i][6] + bwB.z, acc[i][7] + bwB.w};
        *(float4*)&g_h[row * 128 + tx * 4] = o0;
        *(float4*)&g_h[row * 128 + 64 + tx * 4] = o1;
        p1[i] = o0.x * a1A.x + o0.y * a1A.y + o0.z * a1A.z + o0.w * a1A.w +
                o1.x * a1B.x + o1.y * a1B.y + o1.z * a1B.z + o1.w * a1B.w;
        p2[i] = o0.x * a2A.x + o0.y * a2A.y + o0.z * a2A.z + o0.w * a2A.w +
                o1.x * a2B.x + o1.y * a2B.y + o1.z * a2B.z + o1.w * a2B.w;
    }
#pragma unroll
    for (int off = 8; off > 0; off >>= 1) {
#pragma unroll
        for (int i = 0; i < 4; i++) {
            p1[i] += __shfl_down_sync(0xffffffffu, p1[i], off);
            p2[i] += __shfl_down_sync(0xffffffffu, p2[i], off);
        }
    }
    if (tx == 0) {
        float ba0 = ba[0];
#pragma unroll
        for (int i = 0; i < 4; i++) {
            int row = m0 + ty * 4 + i;
            float s1v = p1[i];
            float s2pv = p2[i] + ba0;
            g_s1[row] = s1v;
            g_s2p[row] = s2pv;
            g_u1[row] = expf(s1v);
            g_u2[row] = expf(s2pv);
            g_v1[row] = expf(0.2f * s1v);
            g_v2[row] = expf(0.2f * s2pv);
        }
    }
}

// ---------------- kernel 2: adj -> P (half, gmem) + column sums D ----------------
// grid (4, 32, 8): x = 512-col block, y = 64-row chunk, z = batch. 128 thr, 4 cols/thread.
__global__ __launch_bounds__(128) void k_pack(const int* __restrict__ adj) {
    const int t = threadIdx.x;
    const int jb = blockIdx.x, ic = blockIdx.y, b = blockIdx.z;
    const int i0 = ic * 64;
    const int nb = b * NN;
    __shared__ float s1s[64], u1s[64], v1s[64];
    if (t < 64) {
        s1s[t] = g_s1[nb + i0 + t];
        u1s[t] = g_u1[nb + i0 + t];
        v1s[t] = g_v1[nb + i0 + t];
    }
    __syncthreads();

    const int jloc = jb * 512 + t * 4;
    float s2p[4], u2j[4], v2j[4], accD[4];
#pragma unroll
    for (int q = 0; q < 4; q++) {
        s2p[q] = g_s2p[nb + jloc + q];
        u2j[q] = g_u2[nb + jloc + q];
        v2j[q] = g_v2[nb + jloc + q];
        accD[q] = 0.f;
    }
    const int4* arow = (const int4*)(adj + (size_t)b * NN * NN + (size_t)i0 * NN + jb * 512);
    __half* pbase = g_Ph + (size_t)(nb + i0) * NN + jloc;
    const int stride4 = NN / 4;

#pragma unroll 4
    for (int ii = 0; ii < 64; ii++) {
        int4 av = arow[ii * stride4 + t];
        float s1i = s1s[ii], u1i = u1s[ii], v1i = v1s[ii];
        int e[4] = {av.x, av.y, av.z, av.w};
        float p[4];
#pragma unroll
        for (int q = 0; q < 4; q++) {
            float tt = s1i + s2p[q];
            float pv = (tt > 0.f) ? u1i * u2j[q] : v1i * v2j[q];
            pv = (e[q] > 0) ? pv : 0.f;
            accD[q] += pv;
            p[q] = pv;
        }
        uint2 st;
        st.x = pack_h2(p[0], p[1]);
        st.y = pack_h2(p[2], p[3]);
        *(uint2*)(pbase + (size_t)ii * NN) = st;
    }
#pragma unroll
    for (int q = 0; q < 4; q++) atomicAdd(&g_D[nb + jloc + q], accD[q]);
}

// ---------------- kernel 3: h2h[b][f][j] = half(h[b][j][f] / D[b][j]) (transpose) ----------------
// grid (64, 4, 8), block (32, 8): 32x32 tiles.
__global__ __launch_bounds__(256) void k_scaleT() {
    __shared__ float tile[32][33];
    const int b = blockIdx.z;
    const int j0 = blockIdx.x * 32, f0 = blockIdx.y * 32;
    const int tx = threadIdx.x, ty = threadIdx.y;
    const int nb = b * NN;
#pragma unroll
    for (int q = 0; q < 4; q++) {
        int j = j0 + ty + q * 8;
        tile[ty + q * 8][tx] = g_h[(size_t)(nb + j) * FF + f0 + tx];
    }
    __syncthreads();
    float d = g_D[nb + j0 + tx];
    float inv = (d != 0.f) ? (1.f / d) : 0.f;  // guard fully-masked columns
#pragma unroll
    for (int q = 0; q < 4; q++) {
        int f = f0 + ty + q * 8;
        g_h2h[((size_t)b * FF + f) * NN + j0 + tx] = __float2half_rn(tile[tx][ty + q * 8] * inv);
    }
}

// ---------------- kernel 4: out = relu(P @ h2), fp16 GEMM, 128x128 CTA tile ----------------
// grid (16, 8): 128-row i-block, batch. 512 thr = 16 warps: 4(M, mt=2 -> 32 rows) x 4(N=32).
// A and B tiles both 128 rows x 32 k halfs, stride 40 (conflict-free ldmatrix + LDS).
// Triple-buffered cp.async, 1 barrier/kt. Crossbar per kt: A 32KB + B 32KB + STS 20KB
// for a 128x128 output tile (vs 63KB for 64x128 before -> 33% less per output).
#define ASTRIDE 40
#define T_BYTES (128 * ASTRIDE * 2)  // 10240 per tile (A and B identical shape)

__device__ __forceinline__ void attn_tile(uint32_t aAddr, const __half* __restrict__ H,
                                          int wn, int r, int c, float acc[2][4][4]) {
#pragma unroll
    for (int s = 0; s < 2; s++) {
        unsigned a[2][4];
        ldsm_x4(a[0], aAddr + s * 32);
        ldsm_x4(a[1], aAddr + 16 * ASTRIDE * 2 + s * 32);
#pragma unroll
        for (int nt = 0; nt < 4; nt++) {
            const int f = wn * 32 + nt * 8 + r;
            unsigned b0 = *(const unsigned*)&H[f * ASTRIDE + s * 16 + 2 * c];
            unsigned b1 = *(const unsigned*)&H[f * ASTRIDE + s * 16 + 2 * c + 8];
            mma_fp16(acc[0][nt], a[0], b0, b1);
            mma_fp16(acc[1][nt], a[1], b0, b1);
        }
    }
}

__global__ __launch_bounds__(512) void k_attn(float* __restrict__ out) {
    extern __shared__ char smraw[];
    __half* As = (__half*)smraw;                    // 3 x T_BYTES
    __half* Bs = (__half*)(smraw + 3 * T_BYTES);    // 3 x T_BYTES

    const int b = blockIdx.y;
    const int i0 = blockIdx.x * 128;
    const int t = threadIdx.x;
    const int lane = t & 31, wid = t >> 5;
    const int wm = wid & 3, wn = wid >> 2;
    const int r = lane >> 2, c = lane & 3;
    const int nb = b * NN;

    const __half* aSrc = g_Ph + (size_t)(nb + i0) * NN;
    const __half* bSrc = g_h2h + (size_t)b * FF * NN;

    // cp.async mapping: each tile = 512 chunks of 16B (128 rows x 4 segs); 1/thread.
    const int row = t >> 2, seg = t & 3;
    const __half* agp = aSrc + (size_t)row * NN + seg * 8;
    const __half* bgp = bSrc + (size_t)row * NN + seg * 8;
    unsigned adst = (unsigned)__cvta_generic_to_shared(As + row * ASTRIDE + seg * 8);
    unsigned bdst = (unsigned)__cvta_generic_to_shared(Bs + row * ASTRIDE + seg * 8);

    // ldmatrix A-frag addr (buffer 0): rows wm*32 + (lane&15), 16B-col (lane>>4)
    uint32_t aAddr = (uint32_t)__cvta_generic_to_shared(
        As + (wm * 32 + (lane & 15)) * ASTRIDE + (lane >> 4) * 8);

    float acc[2][4][4];
#pragma unroll
    for (int mt = 0; mt < 2; mt++)
#pragma unroll
        for (int nt = 0; nt < 4; nt++)
#pragma unroll
            for (int q = 0; q < 4; q++) acc[mt][nt][q] = 0.f;

    // prologue: prefetch tiles 0 and 1
#pragma unroll
    for (int p = 0; p < 2; p++) {
        CP_ASYNC16(adst + p * T_BYTES, agp + p * 32);
        CP_ASYNC16(bdst + p * T_BYTES, bgp + p * 32);
        CP_COMMIT();
    }

    const __half* pfA = agp + 2 * 32;
    const __half* pfB = bgp + 2 * 32;

    int cur = 0, pre = 2;
    for (int kt = 0; kt < 63; kt++) {
        CP_WAIT(1);
        __syncthreads();

        if (kt < 62) {
            CP_ASYNC16(adst + pre * T_BYTES, pfA);
            CP_ASYNC16(bdst + pre * T_BYTES, pfB);
            CP_COMMIT();
            pfA += 32;
            pfB += 32;
        }

        attn_tile(aAddr + cur * T_BYTES, Bs + cur * (T_BYTES / 2), wn, r, c, acc);

        cur = (cur == 2) ? 0 : cur + 1;
        pre = (pre == 2) ? 0 : pre + 1;
    }
    CP_WAIT(0);
    __syncthreads();
    attn_tile(aAddr + cur * T_BYTES, Bs + cur * (T_BYTES / 2), wn, r, c, acc);

#pragma unroll
    for (int mt = 0; mt < 2; mt++) {
        const int rA = i0 + wm * 32 + mt * 16 + r, rB = rA + 8;
#pragma unroll
        for (int nt = 0; nt < 4; nt++) {
            int col = wn * 32 + nt * 8 + 2 * c;
            float2 o0 = {fmaxf(acc[mt][nt][0], 0.f), fmaxf(acc[mt][nt][1], 0.f)};
            float2 o1 = {fmaxf(acc[mt][nt][2], 0.f), fmaxf(acc[mt][nt][3], 0.f)};
            *(float2*)&out[(size_t)(nb + rA) * FF + col] = o0;
            *(float2*)&out[(size_t)(nb + rB) * FF + col] = o1;
        }
    }
}

// ---------------- launch ----------------
extern "C" void kernel_launch(void* const* d_in, const int* in_sizes, int n_in,
                              void* d_out, int out_size) {
    const float* x = (const float*)d_in[0];
    const int* adj = (const int*)d_in[1];
    const float* W = (const float*)d_in[2];
    const float* bW = (const float*)d_in[3];
    const float* a1 = (const float*)d_in[4];
    const float* a2 = (const float*)d_in[5];
    const float* ba = (const float*)d_in[6];
    float* out = (float*)d_out;

    const int smem_attn = 6 * T_BYTES;  // 61440 B
    static bool attr_set = false;
    if (!attr_set) {
        cudaFuncSetAttribute(k_attn, cudaFuncAttributeMaxDynamicSharedMemorySize, smem_attn);
        attr_set = true;
    }

    k_gemm_h<<<256, 256>>>(x, W, bW, a1, a2, ba);
    k_pack<<<dim3(4, 32, 8), 128>>>(adj);
    k_scaleT<<<dim3(64, 4, 8), dim3(32, 8)>>>();
    k_attn<<<dim3(16, 8), 512, smem_attn>>>(out);
}